// round 9
// baseline (speedup 1.0000x reference)
#include <cuda_runtime.h>
#include <cstdint>
#include <cstddef>

// ---------------- scratch ----------------
__device__ float g_W1[2048 * 160];      // tf32-rounded w1
__device__ float g_W2[5 * 32 * 2048];   // tf32-rounded w2
__device__ float g_H[8192 * 160];       // tanh(xx@W1), tf32-rounded

__device__ __forceinline__ unsigned f2tf32(float f) {
    unsigned u;
    asm("cvt.rna.tf32.f32 %0, %1;" : "=r"(u) : "f"(f));
    return u;
}

__device__ __forceinline__ void mma_tf32(float c[4], const unsigned a[4],
                                         unsigned b0, unsigned b1) {
    asm volatile(
        "mma.sync.aligned.m16n8k8.row.col.f32.tf32.tf32.f32 "
        "{%0,%1,%2,%3}, {%4,%5,%6,%7}, {%8,%9}, {%0,%1,%2,%3};\n"
        : "+f"(c[0]), "+f"(c[1]), "+f"(c[2]), "+f"(c[3])
        : "r"(a[0]), "r"(a[1]), "r"(a[2]), "r"(a[3]), "r"(b0), "r"(b1));
}

__device__ __forceinline__ void cp16(uint32_t dst, const void* src) {
    asm volatile("cp.async.cg.shared.global [%0], [%1], 16;\n" :: "r"(dst), "l"(src));
}
__device__ __forceinline__ void cp_commit() { asm volatile("cp.async.commit_group;\n"); }
__device__ __forceinline__ void cp_wait0()  { asm volatile("cp.async.wait_group 0;\n" ::: "memory"); }
__device__ __forceinline__ void cp_wait1()  { asm volatile("cp.async.wait_group 1;\n" ::: "memory"); }

__device__ __forceinline__ uint32_t smem_u32(const void* p) {
    return (uint32_t)__cvta_generic_to_shared(p);
}

// ============================================================================
// GEMM1: H[M,160] = tanh( (x + sx*tmx) @ W1[D,160] )
// Block tile 32m x 160n, 256 threads (8 warps: 2m x 4n, warp 16x40).
// 96 KB smem -> 2 CTAs/SM: independent CTAs hide each other's sync bubbles.
// 3-stage cp.async ring on x rows and W1 K-tiles.
// ============================================================================
#define G1_AS   9216                     // 2*32*36*4
#define G1_BS   64512                    // 3*32*168*4
#define G1_XS   14256                    // 3*33*36*4
#define G1_TMX  8192
#define G1_SMEM (G1_AS + G1_BS + G1_XS + G1_TMX)

__global__ void __launch_bounds__(256, 2)
gemm1_kernel(const float* __restrict__ x, const float* __restrict__ state,
             const float* __restrict__ tmx,
             const int* __restrict__ ip, int S, int D, int srows)
{
    extern __shared__ unsigned char sm[];
    unsigned (*As)[32][36]   = reinterpret_cast<unsigned (*)[32][36]>(sm);
    unsigned (*Bs1)[32][168] = reinterpret_cast<unsigned (*)[32][168]>(sm + G1_AS);
    float    (*Xs)[33][36]   = reinterpret_cast<float (*)[33][36]>(sm + G1_AS + G1_BS);
    float*    tmxs           = reinterpret_cast<float*>(sm + G1_AS + G1_BS + G1_XS);

    const int tid  = threadIdx.x;
    const int lane = tid & 31;
    const int warp = tid >> 5;
    const int wm   = warp & 1;    // rows wm*16
    const int wn   = warp >> 1;   // cols wn*40
    const int gid  = lane >> 2;
    const int tg   = lane & 3;
    const int m0   = blockIdx.x * 32;
    const int i1   = srows * ip[0] + 1;

    const float* xprow0 = ((m0 % S) == 0)
        ? state + ((size_t)(m0 / S) * srows + i1) * D
        : x + (size_t)(m0 - 1) * D;

    auto issueX1 = [&](int s) {
        int k0 = s * 32, slot = s % 3;
        {
            int r = tid >> 3, cg = (tid & 7) * 4;   // local rows 1..32 = x rows m0..m0+31
            cp16(smem_u32(&Xs[slot][r + 1][cg]), x + (size_t)(m0 + r) * D + k0 + cg);
        }
        if (tid < 8) {
            int cg = tid * 4;
            cp16(smem_u32(&Xs[slot][0][cg]), xprow0 + k0 + cg);
        }
    };
    auto issueB1 = [&](int s) {
        int k0 = s * 32, slot = s % 3;
        #pragma unroll
        for (int it = 0; it < 5; it++) {
            int e = tid + it * 256;                 // 1280 float4 total
            int r = e / 40, c4 = (e % 40) * 4;
            cp16(smem_u32(&Bs1[slot][r][c4]), g_W1 + (size_t)(k0 + r) * 160 + c4);
        }
    };

    #pragma unroll
    for (int it = 0; it < 2; it++) {
        int e = tid + it * 256;
        cp16(smem_u32(tmxs + e * 4), tmx + e * 4);
    }
    issueX1(0); issueB1(0); cp_commit();
    issueX1(1); issueB1(1); cp_commit();

    float acc1[5][4];
    #pragma unroll
    for (int b = 0; b < 5; b++)
        #pragma unroll
        for (int c = 0; c < 4; c++) acc1[b][c] = 0.f;

    const int nkt = D / 32;
    for (int kt = 0; kt < nkt; kt++) {
        const int slot = kt % 3, buf = kt & 1, k0 = kt * 32;
        if (kt + 1 < nkt) cp_wait1(); else cp_wait0();
        __syncthreads();
        if (kt + 2 < nkt) { issueX1(kt + 2); issueB1(kt + 2); cp_commit(); }

        // mix -> tf32 A tile (32x32)
        {
            int r = tid >> 3, c4 = (tid & 7) * 4;
            float4 xv = *reinterpret_cast<float4*>(&Xs[slot][r + 1][c4]);
            float4 xp = *reinterpret_cast<float4*>(&Xs[slot][r][c4]);
            float4 tv = *reinterpret_cast<float4*>(&tmxs[k0 + c4]);
            uint4 o;
            o.x = f2tf32(xv.x + (xp.x - xv.x) * tv.x);
            o.y = f2tf32(xv.y + (xp.y - xv.y) * tv.y);
            o.z = f2tf32(xv.z + (xp.z - xv.z) * tv.z);
            o.w = f2tf32(xv.w + (xp.w - xv.w) * tv.w);
            *reinterpret_cast<uint4*>(&As[buf][r][c4]) = o;
        }
        __syncthreads();

        #pragma unroll
        for (int kk = 0; kk < 4; kk++) {
            unsigned a[4];
            int ar = wm * 16 + gid;
            int ac = kk * 8 + tg;
            a[0] = As[buf][ar][ac];
            a[1] = As[buf][ar + 8][ac];
            a[2] = As[buf][ar][ac + 4];
            a[3] = As[buf][ar + 8][ac + 4];
            #pragma unroll
            for (int nt = 0; nt < 5; nt++) {
                int bc = wn * 40 + nt * 8 + gid;
                unsigned b0 = Bs1[slot][kk * 8 + tg][bc];
                unsigned b1 = Bs1[slot][kk * 8 + tg + 4][bc];
                mma_tf32(acc1[nt], a, b0, b1);
            }
        }
    }

    #pragma unroll
    for (int nt = 0; nt < 5; nt++) {
        int gc = wn * 40 + nt * 8 + 2 * tg;
        #pragma unroll
        for (int h = 0; h < 2; h++) {
            int gr = m0 + wm * 16 + gid + h * 8;
            float2 v;
            v.x = __uint_as_float(f2tf32(tanhf(acc1[nt][2 * h])));
            v.y = __uint_as_float(f2tf32(tanhf(acc1[nt][2 * h + 1])));
            *reinterpret_cast<float2*>(g_H + (size_t)gr * 160 + gc) = v;
        }
    }
}

// ============================================================================
// GEMM2 + epilogue. Tile 64m x 64n, 5 modes inner, H-slice + W2 double-buffered.
// x/xprev hoisted into registers ONCE (mode-invariant) -> 5x fewer epilogue LDS.
// 256 threads, 54.5 KB smem, __launch_bounds__(256,3).
// Warps: 2(m) x 4(n); warp tile 32m x 16n.
// ============================================================================
#define G2_HS   18432                    // 2*64*36*4
#define G2_BS   18432                    // 2*32*72*4
#define G2_XV   17680                    // 65*68*4
#define G2_SMEM (G2_HS + G2_BS + G2_XV)

__global__ void __launch_bounds__(256, 3)
gemm2_kernel(const float* __restrict__ x, const float* __restrict__ state,
             const float* __restrict__ mk, const float* __restrict__ mw,
             const float* __restrict__ mv, const float* __restrict__ mr,
             const float* __restrict__ mg,
             const int* __restrict__ ip, float* __restrict__ out,
             int S, int D, int srows)
{
    extern __shared__ unsigned char sm[];
    unsigned (*Hs)[64][36] = reinterpret_cast<unsigned (*)[64][36]>(sm);
    unsigned (*Bs)[32][72] = reinterpret_cast<unsigned (*)[32][72]>(sm + G2_HS);
    float    (*Xv)[68]     = reinterpret_cast<float (*)[68]>(sm + G2_HS + G2_BS);

    const int tid  = threadIdx.x;
    const int lane = tid & 31;
    const int warp = tid >> 5;
    const int wm   = warp & 1;     // m: wm*32
    const int wn   = warp >> 1;    // n: wn*16
    const int gid  = lane >> 2;
    const int tg   = lane & 3;
    const int n0   = blockIdx.x * 64;
    const int m0   = blockIdx.y * 64;
    const int i1   = srows * ip[0] + 1;

    const float* xprow0 = ((m0 % S) == 0)
        ? state + ((size_t)(m0 / S) * srows + i1) * D
        : x + (size_t)(m0 - 1) * D;

    auto issueH = [&](int f, int buf) {
        #pragma unroll
        for (int it = 0; it < 2; it++) {
            int e = tid + it * 256;
            int r = e >> 3, c4 = (e & 7) * 4;
            cp16(smem_u32(&Hs[buf][r][c4]),
                 g_H + (size_t)(m0 + r) * 160 + f * 32 + c4);
        }
    };
    auto issueB = [&](int f, int buf) {
        #pragma unroll
        for (int it = 0; it < 2; it++) {
            int e = tid + it * 256;
            int r = e >> 4, c4 = (e & 15) * 4;
            cp16(smem_u32(&Bs[buf][r][c4]),
                 g_W2 + ((size_t)f * 32 + r) * D + n0 + c4);
        }
    };

    // prologue: Xv + (H,B) for f=0 | (H,B) for f=1
    #pragma unroll
    for (int it = 0; it < 5; it++) {
        int u = tid + it * 256;
        if (u < 1040) {
            int r = u >> 4, cg = (u & 15) * 4;
            const float* src = (r == 0) ? xprow0 + n0 + cg
                                        : x + (size_t)(m0 - 1 + r) * D + n0 + cg;
            cp16(smem_u32(&Xv[r][cg]), src);
        }
    }
    issueH(0, 0); issueB(0, 0); cp_commit();
    issueH(1, 1); issueB(1, 1); cp_commit();

    // group 0 (Xv, H0, B0) complete -> hoist x/xprev into registers
    cp_wait1();
    __syncthreads();

    float2 rxv[2][2][2], rdx[2][2][2];     // [mi][nt][h], mode-invariant
    #pragma unroll
    for (int mi = 0; mi < 2; mi++)
        #pragma unroll
        for (int nt = 0; nt < 2; nt++) {
            int lc = wn * 16 + nt * 8 + 2 * tg;
            #pragma unroll
            for (int h = 0; h < 2; h++) {
                int lr = wm * 32 + mi * 16 + gid + h * 8;
                float2 xv = *reinterpret_cast<float2*>(&Xv[lr + 1][lc]);
                float2 xp = *reinterpret_cast<float2*>(&Xv[lr][lc]);
                rxv[mi][nt][h] = xv;
                rdx[mi][nt][h].x = xp.x - xv.x;
                rdx[mi][nt][h].y = xp.y - xv.y;
            }
        }

    #pragma unroll
    for (int f = 0; f < 5; f++) {
        const int buf = f & 1;
        if (f < 4) cp_wait1(); else cp_wait0();
        __syncthreads();

        float acc[2][2][4];
        #pragma unroll
        for (int a = 0; a < 2; a++)
            #pragma unroll
            for (int b = 0; b < 2; b++)
                #pragma unroll
                for (int c = 0; c < 4; c++) acc[a][b][c] = 0.f;

        #pragma unroll
        for (int kk = 0; kk < 4; kk++) {
            unsigned a[2][4];
            #pragma unroll
            for (int mi = 0; mi < 2; mi++) {
                int ar = wm * 32 + mi * 16 + gid;
                int ac = kk * 8 + tg;
                a[mi][0] = Hs[buf][ar][ac];
                a[mi][1] = Hs[buf][ar + 8][ac];
                a[mi][2] = Hs[buf][ar][ac + 4];
                a[mi][3] = Hs[buf][ar + 8][ac + 4];
            }
            #pragma unroll
            for (int nt = 0; nt < 2; nt++) {
                int bc = wn * 16 + nt * 8 + gid;
                unsigned b0 = Bs[buf][kk * 8 + tg][bc];
                unsigned b1 = Bs[buf][kk * 8 + tg + 4][bc];
                mma_tf32(acc[0][nt], a[0], b0, b1);
                mma_tf32(acc[1][nt], a[1], b0, b1);
            }
        }
        __syncthreads();                 // done reading Hs/Bs[buf]
        if (f + 2 <= 4) {                // refill this buffer for mode f+2
            issueH(f + 2, buf);
            issueB(f + 2, buf);
            cp_commit();
        }

        const float* maa = (f == 0) ? mk : (f == 1) ? mw : (f == 2) ? mv
                         : (f == 3) ? mr : mg;

        #pragma unroll
        for (int mi = 0; mi < 2; mi++)
            #pragma unroll
            for (int nt = 0; nt < 2; nt++) {
                int lc = wn * 16 + nt * 8 + 2 * tg;
                int gc = n0 + lc;
                float2 mm = *reinterpret_cast<const float2*>(maa + gc);
                #pragma unroll
                for (int h = 0; h < 2; h++) {
                    int lr = wm * 32 + mi * 16 + gid + h * 8;
                    float2 xv = rxv[mi][nt][h];
                    float2 dx = rdx[mi][nt][h];
                    float y0 = acc[mi][nt][2 * h];
                    float y1 = acc[mi][nt][2 * h + 1];
                    float2 o;
                    o.x = xv.x + dx.x * (mm.x + y0);
                    o.y = xv.y + dx.y * (mm.y + y1);
                    __stcs(reinterpret_cast<float2*>(
                        out + ((size_t)(m0 + lr) * 5 + f) * D + gc), o);
                }
            }
    }
}

// ---------------------------------------------------------------------------
// prep kernel: tf32-round W1/W2 + build new_state
// ---------------------------------------------------------------------------
__global__ void prep_kernel(const float* __restrict__ w1, const float* __restrict__ w2,
                            const float* __restrict__ x, const float* __restrict__ state,
                            const int* __restrict__ ip, float* __restrict__ outs,
                            int n1, int n2, int nb1, int S, int D, int srows, int total)
{
    int bid = blockIdx.x;
    if (bid < nb1) {
        int idx = (bid * 256 + threadIdx.x) * 4;
        if (idx < n1) {
            float4 v = *reinterpret_cast<const float4*>(w1 + idx);
            float4 o;
            o.x = __uint_as_float(f2tf32(v.x)); o.y = __uint_as_float(f2tf32(v.y));
            o.z = __uint_as_float(f2tf32(v.z)); o.w = __uint_as_float(f2tf32(v.w));
            *reinterpret_cast<float4*>(g_W1 + idx) = o;
        }
        if (idx < n2) {
            float4 v = *reinterpret_cast<const float4*>(w2 + idx);
            float4 o;
            o.x = __uint_as_float(f2tf32(v.x)); o.y = __uint_as_float(f2tf32(v.y));
            o.z = __uint_as_float(f2tf32(v.z)); o.w = __uint_as_float(f2tf32(v.w));
            *reinterpret_cast<float4*>(g_W2 + idx) = o;
        }
    } else {
        int idx = ((bid - nb1) * 256 + threadIdx.x) * 4;
        if (idx < total) {
            int i1 = srows * ip[0] + 1;
            int d = idx % D;
            int r = (idx / D) % srows;
            int b = idx / (D * srows);
            float4 v;
            if (r == i1)
                v = *reinterpret_cast<const float4*>(x + ((size_t)b * S + (S - 1)) * D + d);
            else
                v = *reinterpret_cast<const float4*>(state + idx);
            *reinterpret_cast<float4*>(outs + idx) = v;
        }
    }
}

extern "C" void kernel_launch(void* const* d_in, const int* in_sizes, int n_in,
                              void* d_out, int out_size)
{
    const float* x     = (const float*)d_in[0];
    const float* state = (const float*)d_in[1];
    const float* tmx   = (const float*)d_in[2];
    const float* w1    = (const float*)d_in[3];
    const float* w2    = (const float*)d_in[4];
    const float* mk    = (const float*)d_in[5];
    const float* mw    = (const float*)d_in[6];
    const float* mv    = (const float*)d_in[7];
    const float* mr    = (const float*)d_in[8];
    const float* mg    = (const float*)d_in[9];
    const int*   ip    = (const int*)d_in[10];
    float* out = (float*)d_out;

    const int D     = in_sizes[2];
    const int srows = 2 + D / 32;
    const int Bb    = in_sizes[1] / (srows * D);
    const int M     = in_sizes[0] / D;
    const int S     = M / Bb;
    const int n1    = in_sizes[3];
    const int n2    = in_sizes[4];

    static bool attr_done = false;
    if (!attr_done) {
        cudaFuncSetAttribute(gemm1_kernel, cudaFuncAttributeMaxDynamicSharedMemorySize, G1_SMEM);
        cudaFuncSetAttribute(gemm2_kernel, cudaFuncAttributeMaxDynamicSharedMemorySize, G2_SMEM);
        attr_done = true;
    }

    long long main_sz = (long long)M * 5 * D;
    long long st_sz   = (long long)Bb * srows * D;
    int total = ((long long)out_size >= main_sz + st_sz) ? (int)st_sz : 0;

    int nmax = n1 > n2 ? n1 : n2;
    int nb1 = (nmax / 4 + 255) / 256;
    int nb2 = (total / 4 + 255) / 256;
    prep_kernel<<<nb1 + nb2, 256>>>(w1, w2, x, state, ip, out + main_sz,
                                    n1, n2, nb1, S, D, srows, total);
    gemm1_kernel<<<M / 32, 256, G1_SMEM>>>(x, state, tmx, ip, S, D, srows);
    gemm2_kernel<<<dim3(D / 64, M / 64), 256, G2_SMEM>>>(x, state, mk, mw, mv, mr, mg,
                                                         ip, out, S, D, srows);
}

// round 10
// speedup vs baseline: 1.0566x; 1.0566x over previous
#include <cuda_runtime.h>
#include <cstdint>
#include <cstddef>

// ---------------- scratch ----------------
__device__ float g_H[8192 * 160];       // tanh(xx@W1), tf32-rounded

__device__ __forceinline__ unsigned f2tf32(float f) {
    unsigned u;
    asm("cvt.rna.tf32.f32 %0, %1;" : "=r"(u) : "f"(f));
    return u;
}

__device__ __forceinline__ void mma_tf32(float c[4], const unsigned a[4],
                                         unsigned b0, unsigned b1) {
    asm volatile(
        "mma.sync.aligned.m16n8k8.row.col.f32.tf32.tf32.f32 "
        "{%0,%1,%2,%3}, {%4,%5,%6,%7}, {%8,%9}, {%0,%1,%2,%3};\n"
        : "+f"(c[0]), "+f"(c[1]), "+f"(c[2]), "+f"(c[3])
        : "r"(a[0]), "r"(a[1]), "r"(a[2]), "r"(a[3]), "r"(b0), "r"(b1));
}

__device__ __forceinline__ void cp16(uint32_t dst, const void* src) {
    asm volatile("cp.async.cg.shared.global [%0], [%1], 16;\n" :: "r"(dst), "l"(src));
}
__device__ __forceinline__ void cp_commit() { asm volatile("cp.async.commit_group;\n"); }
__device__ __forceinline__ void cp_wait0()  { asm volatile("cp.async.wait_group 0;\n" ::: "memory"); }
__device__ __forceinline__ void cp_wait1()  { asm volatile("cp.async.wait_group 1;\n" ::: "memory"); }

__device__ __forceinline__ uint32_t smem_u32(const void* p) {
    return (uint32_t)__cvta_generic_to_shared(p);
}

// ============================================================================
// GEMM1: H[M,160] = tanh( (x + sx*tmx) @ W1[D,160] )
// 512 threads, 16 warps 4(m)x4(n), block tile 64x160, 3-stage cp.async ring.
// W1 consumed as raw fp32 bits (HW truncates to tf32 in the MMA).
// ============================================================================
#define G1_AS   18432                    // 2*64*36*4
#define G1_BS   64512                    // 3*32*168*4
#define G1_XS   28080                    // 3*65*36*4
#define G1_TMX  8192
#define G1_SMEM (G1_AS + G1_BS + G1_XS + G1_TMX)

__global__ void __launch_bounds__(512)
gemm1_kernel(const float* __restrict__ x, const float* __restrict__ state,
             const float* __restrict__ tmx, const float* __restrict__ w1,
             const int* __restrict__ ip, int S, int D, int srows)
{
    extern __shared__ unsigned char sm[];
    unsigned (*As)[64][36]   = reinterpret_cast<unsigned (*)[64][36]>(sm);
    unsigned (*Bs1)[32][168] = reinterpret_cast<unsigned (*)[32][168]>(sm + G1_AS);
    float    (*Xs)[65][36]   = reinterpret_cast<float (*)[65][36]>(sm + G1_AS + G1_BS);
    float*    tmxs           = reinterpret_cast<float*>(sm + G1_AS + G1_BS + G1_XS);

    const int tid  = threadIdx.x;
    const int lane = tid & 31;
    const int warp = tid >> 5;
    const int wm   = warp & 3;
    const int wn   = warp >> 2;
    const int gid  = lane >> 2;
    const int tg   = lane & 3;
    const int m0   = blockIdx.x * 64;
    const int i1   = srows * ip[0] + 1;

    const float* xprow0 = ((m0 % S) == 0)
        ? state + ((size_t)(m0 / S) * srows + i1) * D
        : x + (size_t)(m0 - 1) * D;

    auto issueX1 = [&](int s) {
        int k0 = s * 32, slot = s % 3;
        {
            int r = tid >> 3, cg = (tid & 7) * 4;
            const float* src = (r == 0) ? xprow0 + k0 + cg
                                        : x + (size_t)(m0 - 1 + r) * D + k0 + cg;
            cp16(smem_u32(&Xs[slot][r][cg]), src);
        }
        if (tid < 8) {
            int cg = tid * 4;
            cp16(smem_u32(&Xs[slot][64][cg]), x + (size_t)(m0 + 63) * D + k0 + cg);
        }
    };
    auto issueB1 = [&](int s) {
        int k0 = s * 32, slot = s % 3;
        #pragma unroll
        for (int it = 0; it < 3; it++) {
            int e = tid + it * 512;
            if (e < 1280) {
                int r = e / 40, c4 = (e % 40) * 4;
                cp16(smem_u32(&Bs1[slot][r][c4]), w1 + (size_t)(k0 + r) * 160 + c4);
            }
        }
    };

    if (tid < D / 4) cp16(smem_u32(tmxs + tid * 4), tmx + tid * 4);
    issueX1(0); issueB1(0); cp_commit();
    issueX1(1); issueB1(1); cp_commit();

    float acc1[5][4];
    #pragma unroll
    for (int b = 0; b < 5; b++)
        #pragma unroll
        for (int c = 0; c < 4; c++) acc1[b][c] = 0.f;

    const int nkt = D / 32;
    for (int kt = 0; kt < nkt; kt++) {
        const int slot = kt % 3, buf = kt & 1, k0 = kt * 32;
        if (kt + 1 < nkt) cp_wait1(); else cp_wait0();
        __syncthreads();
        if (kt + 2 < nkt) { issueX1(kt + 2); issueB1(kt + 2); cp_commit(); }

        {
            int r = tid >> 3, c4 = (tid & 7) * 4;
            float4 xv = *reinterpret_cast<float4*>(&Xs[slot][r + 1][c4]);
            float4 xp = *reinterpret_cast<float4*>(&Xs[slot][r][c4]);
            float4 tv = *reinterpret_cast<float4*>(&tmxs[k0 + c4]);
            uint4 o;
            o.x = f2tf32(xv.x + (xp.x - xv.x) * tv.x);
            o.y = f2tf32(xv.y + (xp.y - xv.y) * tv.y);
            o.z = f2tf32(xv.z + (xp.z - xv.z) * tv.z);
            o.w = f2tf32(xv.w + (xp.w - xv.w) * tv.w);
            *reinterpret_cast<uint4*>(&As[buf][r][c4]) = o;
        }
        __syncthreads();

        #pragma unroll
        for (int kk = 0; kk < 4; kk++) {
            unsigned a[4];
            int ar = wm * 16 + gid;
            int ac = kk * 8 + tg;
            a[0] = As[buf][ar][ac];
            a[1] = As[buf][ar + 8][ac];
            a[2] = As[buf][ar][ac + 4];
            a[3] = As[buf][ar + 8][ac + 4];
            #pragma unroll
            for (int nt = 0; nt < 5; nt++) {
                int bc = wn * 40 + nt * 8 + gid;
                unsigned b0 = Bs1[slot][kk * 8 + tg][bc];
                unsigned b1 = Bs1[slot][kk * 8 + tg + 4][bc];
                mma_tf32(acc1[nt], a, b0, b1);
            }
        }
    }

    #pragma unroll
    for (int nt = 0; nt < 5; nt++) {
        int gc = wn * 40 + nt * 8 + 2 * tg;
        #pragma unroll
        for (int h = 0; h < 2; h++) {
            int gr = m0 + wm * 16 + gid + h * 8;
            float2 v;
            v.x = __uint_as_float(f2tf32(tanhf(acc1[nt][2 * h])));
            v.y = __uint_as_float(f2tf32(tanhf(acc1[nt][2 * h + 1])));
            *reinterpret_cast<float2*>(g_H + (size_t)gr * 160 + gc) = v;
        }
    }
}

// ============================================================================
// GEMM2 + epilogue. Tile 64m x 64n, 5 modes inner.
// Triple-buffered (H-slice, W2-slice) -> ONE __syncthreads per mode.
// x/xprev hoisted into registers once (mode-invariant).
// W2 consumed as raw fp32 bits. 73 KB smem -> 3 CTAs/SM.
// Warps: 2(m) x 4(n); warp tile 32m x 16n.
// ============================================================================
#define G2_HS   27648                    // 3*64*36*4
#define G2_BS   27648                    // 3*32*72*4
#define G2_XV   17680                    // 65*68*4
#define G2_SMEM (G2_HS + G2_BS + G2_XV)

__global__ void __launch_bounds__(256, 3)
gemm2_kernel(const float* __restrict__ x, const float* __restrict__ state,
             const float* __restrict__ w2,
             const float* __restrict__ mk, const float* __restrict__ mw,
             const float* __restrict__ mv, const float* __restrict__ mr,
             const float* __restrict__ mg,
             const int* __restrict__ ip, float* __restrict__ out,
             int S, int D, int srows)
{
    extern __shared__ unsigned char sm[];
    unsigned (*Hs)[64][36] = reinterpret_cast<unsigned (*)[64][36]>(sm);
    unsigned (*Bs)[32][72] = reinterpret_cast<unsigned (*)[32][72]>(sm + G2_HS);
    float    (*Xv)[68]     = reinterpret_cast<float (*)[68]>(sm + G2_HS + G2_BS);

    const int tid  = threadIdx.x;
    const int lane = tid & 31;
    const int warp = tid >> 5;
    const int wm   = warp & 1;     // m: wm*32
    const int wn   = warp >> 1;    // n: wn*16
    const int gid  = lane >> 2;
    const int tg   = lane & 3;
    const int n0   = blockIdx.x * 64;
    const int m0   = blockIdx.y * 64;
    const int i1   = srows * ip[0] + 1;

    const float* xprow0 = ((m0 % S) == 0)
        ? state + ((size_t)(m0 / S) * srows + i1) * D
        : x + (size_t)(m0 - 1) * D;

    auto issueH = [&](int f) {
        int slot = f % 3;
        #pragma unroll
        for (int it = 0; it < 2; it++) {
            int e = tid + it * 256;
            int r = e >> 3, c4 = (e & 7) * 4;
            cp16(smem_u32(&Hs[slot][r][c4]),
                 g_H + (size_t)(m0 + r) * 160 + f * 32 + c4);
        }
    };
    auto issueB = [&](int f) {
        int slot = f % 3;
        #pragma unroll
        for (int it = 0; it < 2; it++) {
            int e = tid + it * 256;
            int r = e >> 4, c4 = (e & 15) * 4;
            cp16(smem_u32(&Bs[slot][r][c4]),
                 w2 + ((size_t)f * 32 + r) * D + n0 + c4);
        }
    };

    // prologue: group0 = {Xv, H0, B0}; group1 = {H1, B1}
    #pragma unroll
    for (int it = 0; it < 5; it++) {
        int u = tid + it * 256;
        if (u < 1040) {
            int r = u >> 4, cg = (u & 15) * 4;
            const float* src = (r == 0) ? xprow0 + n0 + cg
                                        : x + (size_t)(m0 - 1 + r) * D + n0 + cg;
            cp16(smem_u32(&Xv[r][cg]), src);
        }
    }
    issueH(0); issueB(0); cp_commit();
    issueH(1); issueB(1); cp_commit();

    // group0 complete -> hoist x/xprev into registers
    cp_wait1();
    __syncthreads();

    float2 rxv[2][2][2], rdx[2][2][2];     // [mi][nt][h], mode-invariant
    #pragma unroll
    for (int mi = 0; mi < 2; mi++)
        #pragma unroll
        for (int nt = 0; nt < 2; nt++) {
            int lc = wn * 16 + nt * 8 + 2 * tg;
            #pragma unroll
            for (int h = 0; h < 2; h++) {
                int lr = wm * 32 + mi * 16 + gid + h * 8;
                float2 xv = *reinterpret_cast<float2*>(&Xv[lr + 1][lc]);
                float2 xp = *reinterpret_cast<float2*>(&Xv[lr][lc]);
                rxv[mi][nt][h] = xv;
                rdx[mi][nt][h].x = xp.x - xv.x;
                rdx[mi][nt][h].y = xp.y - xv.y;
            }
        }

    #pragma unroll
    for (int f = 0; f < 5; f++) {
        const int slot = f % 3;
        if (f > 0) {
            if (f < 4) cp_wait1(); else cp_wait0();   // group f complete
            __syncthreads();                           // all warps done with slot (f-1)%3
        }
        if (f + 2 <= 4) {                              // refill slot (f+2)%3 = slot read in f-1
            issueH(f + 2);
            issueB(f + 2);
            cp_commit();
        }

        float acc[2][2][4];
        #pragma unroll
        for (int a = 0; a < 2; a++)
            #pragma unroll
            for (int b = 0; b < 2; b++)
                #pragma unroll
                for (int c = 0; c < 4; c++) acc[a][b][c] = 0.f;

        #pragma unroll
        for (int kk = 0; kk < 4; kk++) {
            unsigned a[2][4];
            #pragma unroll
            for (int mi = 0; mi < 2; mi++) {
                int ar = wm * 32 + mi * 16 + gid;
                int ac = kk * 8 + tg;
                a[mi][0] = Hs[slot][ar][ac];
                a[mi][1] = Hs[slot][ar + 8][ac];
                a[mi][2] = Hs[slot][ar][ac + 4];
                a[mi][3] = Hs[slot][ar + 8][ac + 4];
            }
            #pragma unroll
            for (int nt = 0; nt < 2; nt++) {
                int bc = wn * 16 + nt * 8 + gid;
                unsigned b0 = Bs[slot][kk * 8 + tg][bc];
                unsigned b1 = Bs[slot][kk * 8 + tg + 4][bc];
                mma_tf32(acc[0][nt], a[0], b0, b1);
                mma_tf32(acc[1][nt], a[1], b0, b1);
            }
        }

        const float* maa = (f == 0) ? mk : (f == 1) ? mw : (f == 2) ? mv
                         : (f == 3) ? mr : mg;

        #pragma unroll
        for (int mi = 0; mi < 2; mi++)
            #pragma unroll
            for (int nt = 0; nt < 2; nt++) {
                int lc = wn * 16 + nt * 8 + 2 * tg;
                int gc = n0 + lc;
                float2 mm = *reinterpret_cast<const float2*>(maa + gc);
                #pragma unroll
                for (int h = 0; h < 2; h++) {
                    int lr = wm * 32 + mi * 16 + gid + h * 8;
                    float2 xv = rxv[mi][nt][h];
                    float2 dx = rdx[mi][nt][h];
                    float y0 = acc[mi][nt][2 * h];
                    float y1 = acc[mi][nt][2 * h + 1];
                    float2 o;
                    o.x = xv.x + dx.x * (mm.x + y0);
                    o.y = xv.y + dx.y * (mm.y + y1);
                    __stcs(reinterpret_cast<float2*>(
                        out + ((size_t)(m0 + lr) * 5 + f) * D + gc), o);
                }
            }
    }
}

// ---------------------------------------------------------------------------
// state kernel: copy state, replace row i1 with x[:, S-1, :]
// ---------------------------------------------------------------------------
__global__ void state_kernel(const float* __restrict__ x, const float* __restrict__ state,
                             const int* __restrict__ ip, float* __restrict__ outs,
                             int S, int D, int srows, int total)
{
    int idx = (blockIdx.x * blockDim.x + threadIdx.x) * 4;
    if (idx >= total) return;
    int i1 = srows * ip[0] + 1;
    int d = idx % D;
    int r = (idx / D) % srows;
    int b = idx / (D * srows);
    float4 v;
    if (r == i1)
        v = *reinterpret_cast<const float4*>(x + ((size_t)b * S + (S - 1)) * D + d);
    else
        v = *reinterpret_cast<const float4*>(state + idx);
    *reinterpret_cast<float4*>(outs + idx) = v;
}

extern "C" void kernel_launch(void* const* d_in, const int* in_sizes, int n_in,
                              void* d_out, int out_size)
{
    const float* x     = (const float*)d_in[0];
    const float* state = (const float*)d_in[1];
    const float* tmx   = (const float*)d_in[2];
    const float* w1    = (const float*)d_in[3];
    const float* w2    = (const float*)d_in[4];
    const float* mk    = (const float*)d_in[5];
    const float* mw    = (const float*)d_in[6];
    const float* mv    = (const float*)d_in[7];
    const float* mr    = (const float*)d_in[8];
    const float* mg    = (const float*)d_in[9];
    const int*   ip    = (const int*)d_in[10];
    float* out = (float*)d_out;

    const int D     = in_sizes[2];
    const int srows = 2 + D / 32;
    const int Bb    = in_sizes[1] / (srows * D);
    const int M     = in_sizes[0] / D;
    const int S     = M / Bb;

    static bool attr_done = false;
    if (!attr_done) {
        cudaFuncSetAttribute(gemm1_kernel, cudaFuncAttributeMaxDynamicSharedMemorySize, G1_SMEM);
        cudaFuncSetAttribute(gemm2_kernel, cudaFuncAttributeMaxDynamicSharedMemorySize, G2_SMEM);
        attr_done = true;
    }

    long long main_sz = (long long)M * 5 * D;
    long long st_sz   = (long long)Bb * srows * D;
    int total = ((long long)out_size >= main_sz + st_sz) ? (int)st_sz : 0;

    gemm1_kernel<<<M / 64, 512, G1_SMEM>>>(x, state, tmx, w1, ip, S, D, srows);
    gemm2_kernel<<<dim3(D / 64, M / 64), 256, G2_SMEM>>>(x, state, w2, mk, mw, mv, mr, mg,
                                                         ip, out, S, D, srows);
    if (total > 0)
        state_kernel<<<(total / 4 + 255) / 256, 256>>>(x, state, ip, out + main_sz,
                                                       S, D, srows, total);
}

// round 11
// speedup vs baseline: 1.1166x; 1.0568x over previous
#include <cuda_runtime.h>
#include <cstdint>
#include <cstddef>

// ---------------- scratch ----------------
__device__ float g_H[8192 * 160];       // tanh(xx@W1), tf32-rounded

__device__ __forceinline__ unsigned f2tf32(float f) {
    unsigned u;
    asm("cvt.rna.tf32.f32 %0, %1;" : "=r"(u) : "f"(f));
    return u;
}

__device__ __forceinline__ void mma_tf32(float c[4], const unsigned a[4],
                                         unsigned b0, unsigned b1) {
    asm volatile(
        "mma.sync.aligned.m16n8k8.row.col.f32.tf32.tf32.f32 "
        "{%0,%1,%2,%3}, {%4,%5,%6,%7}, {%8,%9}, {%0,%1,%2,%3};\n"
        : "+f"(c[0]), "+f"(c[1]), "+f"(c[2]), "+f"(c[3])
        : "r"(a[0]), "r"(a[1]), "r"(a[2]), "r"(a[3]), "r"(b0), "r"(b1));
}

__device__ __forceinline__ void cp16(uint32_t dst, const void* src) {
    asm volatile("cp.async.cg.shared.global [%0], [%1], 16;\n" :: "r"(dst), "l"(src));
}
__device__ __forceinline__ void cp_commit() { asm volatile("cp.async.commit_group;\n"); }
__device__ __forceinline__ void cp_wait0()  { asm volatile("cp.async.wait_group 0;\n" ::: "memory"); }
__device__ __forceinline__ void cp_wait1()  { asm volatile("cp.async.wait_group 1;\n" ::: "memory"); }

__device__ __forceinline__ uint32_t smem_u32(const void* p) {
    return (uint32_t)__cvta_generic_to_shared(p);
}

// ============================================================================
// GEMM1: H[M,160] = tanh( (x + sx*tmx) @ W1[D,160] )
// 512 threads, 16 warps 4(m)x4(n), block tile 64x160.
// K-step 64, 32 iterations, ONE __syncthreads per iteration.
// 3-slot rings for W1 K-tiles (Bs1) and x rows (Xs); A double-buffered.
// W1 consumed as raw fp32 bits (HW truncates to tf32 in the MMA).
// ============================================================================
#define G1_AS   34816                    // 2*64*68*4
#define G1_BS   129024                   // 3*64*168*4
#define G1_XS   53040                    // 3*65*68*4
#define G1_TMX  8192
#define G1_SMEM (G1_AS + G1_BS + G1_XS + G1_TMX)

__global__ void __launch_bounds__(512)
gemm1_kernel(const float* __restrict__ x, const float* __restrict__ state,
             const float* __restrict__ tmx, const float* __restrict__ w1,
             const int* __restrict__ ip, int S, int D, int srows)
{
    extern __shared__ unsigned char sm[];
    unsigned (*As)[64][68]   = reinterpret_cast<unsigned (*)[64][68]>(sm);
    unsigned (*Bs1)[64][168] = reinterpret_cast<unsigned (*)[64][168]>(sm + G1_AS);
    float    (*Xs)[65][68]   = reinterpret_cast<float (*)[65][68]>(sm + G1_AS + G1_BS);
    float*    tmxs           = reinterpret_cast<float*>(sm + G1_AS + G1_BS + G1_XS);

    const int tid  = threadIdx.x;
    const int lane = tid & 31;
    const int warp = tid >> 5;
    const int wm   = warp & 3;    // rows wm*16
    const int wn   = warp >> 2;   // cols wn*40
    const int gid  = lane >> 2;
    const int tg   = lane & 3;
    const int m0   = blockIdx.x * 64;
    const int i1   = srows * ip[0] + 1;

    const float* xprow0 = ((m0 % S) == 0)
        ? state + ((size_t)(m0 / S) * srows + i1) * D
        : x + (size_t)(m0 - 1) * D;

    // stage s covers K columns [s*64, s*64+64)
    auto issueX1 = [&](int s) {
        int k0 = s * 64, slot = s % 3;
        #pragma unroll
        for (int it = 0; it < 2; it++) {
            int u = tid + it * 512;
            int r = u >> 4, cg = (u & 15) * 4;
            const float* src = (r == 0) ? xprow0 + k0 + cg
                                        : x + (size_t)(m0 - 1 + r) * D + k0 + cg;
            cp16(smem_u32(&Xs[slot][r][cg]), src);
        }
        if (tid < 16) {
            int cg = tid * 4;
            cp16(smem_u32(&Xs[slot][64][cg]), x + (size_t)(m0 + 63) * D + k0 + cg);
        }
    };
    auto issueB1 = [&](int s) {
        int k0 = s * 64, slot = s % 3;
        #pragma unroll
        for (int it = 0; it < 5; it++) {
            int e = tid + it * 512;              // 2560 float4 = 64 rows x 40
            int r = e / 40, c4 = (e % 40) * 4;
            cp16(smem_u32(&Bs1[slot][r][c4]), w1 + (size_t)(k0 + r) * 160 + c4);
        }
    };
    // convert stage s (Xs[slot] -> tf32 mixed tile in As[s&1])
    auto convertA = [&](int s) {
        int k0 = s * 64, slot = s % 3, buf = s & 1;
        #pragma unroll
        for (int it = 0; it < 2; it++) {
            int e = tid + it * 512;
            int r = e >> 4, c4 = (e & 15) * 4;
            float4 xv = *reinterpret_cast<float4*>(&Xs[slot][r + 1][c4]);
            float4 xp = *reinterpret_cast<float4*>(&Xs[slot][r][c4]);
            float4 tv = *reinterpret_cast<float4*>(&tmxs[k0 + c4]);
            uint4 o;
            o.x = f2tf32(xv.x + (xp.x - xv.x) * tv.x);
            o.y = f2tf32(xv.y + (xp.y - xv.y) * tv.y);
            o.z = f2tf32(xv.z + (xp.z - xv.z) * tv.z);
            o.w = f2tf32(xv.w + (xp.w - xv.w) * tv.w);
            *reinterpret_cast<uint4*>(&As[buf][r][c4]) = o;
        }
    };

    if (tid < D / 4) cp16(smem_u32(tmxs + tid * 4), tmx + tid * 4);
    issueX1(0); issueB1(0); cp_commit();
    issueX1(1); issueB1(1); cp_commit();

    float acc1[5][4];
    #pragma unroll
    for (int b = 0; b < 5; b++)
        #pragma unroll
        for (int c = 0; c < 4; c++) acc1[b][c] = 0.f;

    // prologue: group0 done -> convert A(0), sync
    cp_wait1();
    __syncthreads();
    convertA(0);
    __syncthreads();

    const int nkt = D / 64;   // 32
    for (int kt = 0; kt < nkt; kt++) {
        const int buf = kt & 1, slot = kt % 3;

        // prefetch stage kt+2 into slot (kt+2)%3 (last read at mma kt-1, synced)
        if (kt + 2 < nkt) { issueX1(kt + 2); issueB1(kt + 2); cp_commit(); }

        // convert stage kt+1 into As[buf^1] (nobody reads it until next iter)
        if (kt + 1 < nkt) {
            if (kt + 2 < nkt) cp_wait1(); else cp_wait0();   // group kt+1 complete
            convertA(kt + 1);
        }

        // MMA on stage kt
        #pragma unroll
        for (int kk = 0; kk < 8; kk++) {
            unsigned a[4];
            int ar = wm * 16 + gid;
            int ac = kk * 8 + tg;
            a[0] = As[buf][ar][ac];
            a[1] = As[buf][ar + 8][ac];
            a[2] = As[buf][ar][ac + 4];
            a[3] = As[buf][ar + 8][ac + 4];
            #pragma unroll
            for (int nt = 0; nt < 5; nt++) {
                int bc = wn * 40 + nt * 8 + gid;
                unsigned b0 = Bs1[slot][kk * 8 + tg][bc];
                unsigned b1 = Bs1[slot][kk * 8 + tg + 4][bc];
                mma_tf32(acc1[nt], a, b0, b1);
            }
        }
        __syncthreads();   // As[buf]/Bs1[slot] reads done; As[buf^1] writes visible
    }

    #pragma unroll
    for (int nt = 0; nt < 5; nt++) {
        int gc = wn * 40 + nt * 8 + 2 * tg;
        #pragma unroll
        for (int h = 0; h < 2; h++) {
            int gr = m0 + wm * 16 + gid + h * 8;
            float2 v;
            v.x = __uint_as_float(f2tf32(tanhf(acc1[nt][2 * h])));
            v.y = __uint_as_float(f2tf32(tanhf(acc1[nt][2 * h + 1])));
            *reinterpret_cast<float2*>(g_H + (size_t)gr * 160 + gc) = v;
        }
    }
}

// ============================================================================
// GEMM2 + epilogue. Tile 64m x 64n, 5 modes inner.
// Triple-buffered (H-slice, W2-slice) -> ONE __syncthreads per mode.
// x/xprev hoisted into registers once (mode-invariant).
// W2 consumed as raw fp32 bits. 73 KB smem -> 3 CTAs/SM.
// Warps: 2(m) x 4(n); warp tile 32m x 16n.
// ============================================================================
#define G2_HS   27648                    // 3*64*36*4
#define G2_BS   27648                    // 3*32*72*4
#define G2_XV   17680                    // 65*68*4
#define G2_SMEM (G2_HS + G2_BS + G2_XV)

__global__ void __launch_bounds__(256, 3)
gemm2_kernel(const float* __restrict__ x, const float* __restrict__ state,
             const float* __restrict__ w2,
             const float* __restrict__ mk, const float* __restrict__ mw,
             const float* __restrict__ mv, const float* __restrict__ mr,
             const float* __restrict__ mg,
             const int* __restrict__ ip, float* __restrict__ out,
             int S, int D, int srows)
{
    extern __shared__ unsigned char sm[];
    unsigned (*Hs)[64][36] = reinterpret_cast<unsigned (*)[64][36]>(sm);
    unsigned (*Bs)[32][72] = reinterpret_cast<unsigned (*)[32][72]>(sm + G2_HS);
    float    (*Xv)[68]     = reinterpret_cast<float (*)[68]>(sm + G2_HS + G2_BS);

    const int tid  = threadIdx.x;
    const int lane = tid & 31;
    const int warp = tid >> 5;
    const int wm   = warp & 1;     // m: wm*32
    const int wn   = warp >> 1;    // n: wn*16
    const int gid  = lane >> 2;
    const int tg   = lane & 3;
    const int n0   = blockIdx.x * 64;
    const int m0   = blockIdx.y * 64;
    const int i1   = srows * ip[0] + 1;

    const float* xprow0 = ((m0 % S) == 0)
        ? state + ((size_t)(m0 / S) * srows + i1) * D
        : x + (size_t)(m0 - 1) * D;

    auto issueH = [&](int f) {
        int slot = f % 3;
        #pragma unroll
        for (int it = 0; it < 2; it++) {
            int e = tid + it * 256;
            int r = e >> 3, c4 = (e & 7) * 4;
            cp16(smem_u32(&Hs[slot][r][c4]),
                 g_H + (size_t)(m0 + r) * 160 + f * 32 + c4);
        }
    };
    auto issueB = [&](int f) {
        int slot = f % 3;
        #pragma unroll
        for (int it = 0; it < 2; it++) {
            int e = tid + it * 256;
            int r = e >> 4, c4 = (e & 15) * 4;
            cp16(smem_u32(&Bs[slot][r][c4]),
                 w2 + ((size_t)f * 32 + r) * D + n0 + c4);
        }
    };

    #pragma unroll
    for (int it = 0; it < 5; it++) {
        int u = tid + it * 256;
        if (u < 1040) {
            int r = u >> 4, cg = (u & 15) * 4;
            const float* src = (r == 0) ? xprow0 + n0 + cg
                                        : x + (size_t)(m0 - 1 + r) * D + n0 + cg;
            cp16(smem_u32(&Xv[r][cg]), src);
        }
    }
    issueH(0); issueB(0); cp_commit();
    issueH(1); issueB(1); cp_commit();

    cp_wait1();
    __syncthreads();

    float2 rxv[2][2][2], rdx[2][2][2];     // [mi][nt][h], mode-invariant
    #pragma unroll
    for (int mi = 0; mi < 2; mi++)
        #pragma unroll
        for (int nt = 0; nt < 2; nt++) {
            int lc = wn * 16 + nt * 8 + 2 * tg;
            #pragma unroll
            for (int h = 0; h < 2; h++) {
                int lr = wm * 32 + mi * 16 + gid + h * 8;
                float2 xv = *reinterpret_cast<float2*>(&Xv[lr + 1][lc]);
                float2 xp = *reinterpret_cast<float2*>(&Xv[lr][lc]);
                rxv[mi][nt][h] = xv;
                rdx[mi][nt][h].x = xp.x - xv.x;
                rdx[mi][nt][h].y = xp.y - xv.y;
            }
        }

    #pragma unroll
    for (int f = 0; f < 5; f++) {
        const int slot = f % 3;
        if (f > 0) {
            if (f < 4) cp_wait1(); else cp_wait0();
            __syncthreads();
        }
        if (f + 2 <= 4) {
            issueH(f + 2);
            issueB(f + 2);
            cp_commit();
        }

        float acc[2][2][4];
        #pragma unroll
        for (int a = 0; a < 2; a++)
            #pragma unroll
            for (int b = 0; b < 2; b++)
                #pragma unroll
                for (int c = 0; c < 4; c++) acc[a][b][c] = 0.f;

        #pragma unroll
        for (int kk = 0; kk < 4; kk++) {
            unsigned a[2][4];
            #pragma unroll
            for (int mi = 0; mi < 2; mi++) {
                int ar = wm * 32 + mi * 16 + gid;
                int ac = kk * 8 + tg;
                a[mi][0] = Hs[slot][ar][ac];
                a[mi][1] = Hs[slot][ar + 8][ac];
                a[mi][2] = Hs[slot][ar][ac + 4];
                a[mi][3] = Hs[slot][ar + 8][ac + 4];
            }
            #pragma unroll
            for (int nt = 0; nt < 2; nt++) {
                int bc = wn * 16 + nt * 8 + gid;
                unsigned b0 = Bs[slot][kk * 8 + tg][bc];
                unsigned b1 = Bs[slot][kk * 8 + tg + 4][bc];
                mma_tf32(acc[0][nt], a[0], b0, b1);
                mma_tf32(acc[1][nt], a[1], b0, b1);
            }
        }

        const float* maa = (f == 0) ? mk : (f == 1) ? mw : (f == 2) ? mv
                         : (f == 3) ? mr : mg;

        #pragma unroll
        for (int nt = 0; nt < 2; nt++) {
            int lc = wn * 16 + nt * 8 + 2 * tg;
            int gc = n0 + lc;
            float2 mm = *reinterpret_cast<const float2*>(maa + gc);
            #pragma unroll
            for (int mi = 0; mi < 2; mi++)
                #pragma unroll
                for (int h = 0; h < 2; h++) {
                    int lr = wm * 32 + mi * 16 + gid + h * 8;
                    float2 xv = rxv[mi][nt][h];
                    float2 dx = rdx[mi][nt][h];
                    float y0 = acc[mi][nt][2 * h];
                    float y1 = acc[mi][nt][2 * h + 1];
                    float2 o;
                    o.x = xv.x + dx.x * (mm.x + y0);
                    o.y = xv.y + dx.y * (mm.y + y1);
                    __stcs(reinterpret_cast<float2*>(
                        out + ((size_t)(m0 + lr) * 5 + f) * D + gc), o);
                }
        }
    }
}

// ---------------------------------------------------------------------------
// state kernel: copy state, replace row i1 with x[:, S-1, :]
// ---------------------------------------------------------------------------
__global__ void state_kernel(const float* __restrict__ x, const float* __restrict__ state,
                             const int* __restrict__ ip, float* __restrict__ outs,
                             int S, int D, int srows, int total)
{
    int idx = (blockIdx.x * blockDim.x + threadIdx.x) * 4;
    if (idx >= total) return;
    int i1 = srows * ip[0] + 1;
    int d = idx % D;
    int r = (idx / D) % srows;
    int b = idx / (D * srows);
    float4 v;
    if (r == i1)
        v = *reinterpret_cast<const float4*>(x + ((size_t)b * S + (S - 1)) * D + d);
    else
        v = *reinterpret_cast<const float4*>(state + idx);
    *reinterpret_cast<float4*>(outs + idx) = v;
}

extern "C" void kernel_launch(void* const* d_in, const int* in_sizes, int n_in,
                              void* d_out, int out_size)
{
    const float* x     = (const float*)d_in[0];
    const float* state = (const float*)d_in[1];
    const float* tmx   = (const float*)d_in[2];
    const float* w1    = (const float*)d_in[3];
    const float* w2    = (const float*)d_in[4];
    const float* mk    = (const float*)d_in[5];
    const float* mw    = (const float*)d_in[6];
    const float* mv    = (const float*)d_in[7];
    const float* mr    = (const float*)d_in[8];
    const float* mg    = (const float*)d_in[9];
    const int*   ip    = (const int*)d_in[10];
    float* out = (float*)d_out;

    const int D     = in_sizes[2];
    const int srows = 2 + D / 32;
    const int Bb    = in_sizes[1] / (srows * D);
    const int M     = in_sizes[0] / D;
    const int S     = M / Bb;

    static bool attr_done = false;
    if (!attr_done) {
        cudaFuncSetAttribute(gemm1_kernel, cudaFuncAttributeMaxDynamicSharedMemorySize, G1_SMEM);
        cudaFuncSetAttribute(gemm2_kernel, cudaFuncAttributeMaxDynamicSharedMemorySize, G2_SMEM);
        attr_done = true;
    }

    long long main_sz = (long long)M * 5 * D;
    long long st_sz   = (long long)Bb * srows * D;
    int total = ((long long)out_size >= main_sz + st_sz) ? (int)st_sz : 0;

    gemm1_kernel<<<M / 64, 512, G1_SMEM>>>(x, state, tmx, w1, ip, S, D, srows);
    gemm2_kernel<<<dim3(D / 64, M / 64), 256, G2_SMEM>>>(x, state, w2, mk, mw, mv, mr, mg,
                                                         ip, out, S, D, srows);
    if (total > 0)
        state_kernel<<<(total / 4 + 255) / 256, 256>>>(x, state, ip, out + main_sz,
                                                       S, D, srows, total);
}